// round 8
// baseline (speedup 1.0000x reference)
#include <cuda_runtime.h>
#include <cuda_bf16.h>
#include <cstdint>

// Polynomial attention deg-2, B=2 H=16 S=2048 D=64 fp32.
// GEMM1: bf16 2-term split, mma.m16n8k16. GEMM2: tf32 m16n8k8 (A via shuffles).
// 128-thread CTAs (4 warps x 32 rows), BT=32, double-buffered, 2 CTAs/SM.

#define SLEN 2048
#define DDIM 64
#define BM 128
#define BT 32
#define NITER (SLEN / BT)
#define NTHREADS 128
#define EPS_CLAMP 1e-4f

#define LDQ2 36   // u32 ld: bank = 4*tq+tc, conflict-free
#define LDK2 36
#define LDV 72    // f32 ld: bank = 8*tc+tq, conflict-free

// smem offsets (4-byte units)
#define OF_QH 0
#define OF_QL (OF_QH + BM * LDQ2)
#define OF_KH (OF_QL + BM * LDQ2)          // [2][BT][36]
#define OF_KL (OF_KH + 2 * BT * LDK2)
#define OF_V  (OF_KL + 2 * BT * LDK2)      // [2][BT][72] f32
#define SMEM_U32 (OF_V + 2 * BT * LDV)
#define SMEM_BYTES (SMEM_U32 * 4)

__device__ __forceinline__ float tf32_rna(float x) {
    uint32_t u;
    asm("cvt.rna.tf32.f32 %0, %1;" : "=r"(u) : "f"(x));
    return __uint_as_float(u);
}
__device__ __forceinline__ uint32_t packbf(float hi, float lo) {
    uint32_t u;
    asm("cvt.rn.bf16x2.f32 %0, %1, %2;" : "=r"(u) : "f"(hi), "f"(lo));
    return u;
}
__device__ __forceinline__ float bfrt(float x) {
    return __bfloat162float(__float2bfloat16(x));
}
__device__ __forceinline__ void mma16(float* d, const uint32_t* a, const uint32_t* b) {
    asm("mma.sync.aligned.m16n8k16.row.col.f32.bf16.bf16.f32 "
        "{%0,%1,%2,%3}, {%4,%5,%6,%7}, {%8,%9}, {%0,%1,%2,%3};"
        : "+f"(d[0]), "+f"(d[1]), "+f"(d[2]), "+f"(d[3])
        : "r"(a[0]), "r"(a[1]), "r"(a[2]), "r"(a[3]), "r"(b[0]), "r"(b[1]));
}
__device__ __forceinline__ void mma8(float* d, const uint32_t* a, const uint32_t* b) {
    asm("mma.sync.aligned.m16n8k8.row.col.f32.tf32.tf32.f32 "
        "{%0,%1,%2,%3}, {%4,%5,%6,%7}, {%8,%9}, {%0,%1,%2,%3};"
        : "+f"(d[0]), "+f"(d[1]), "+f"(d[2]), "+f"(d[3])
        : "r"(a[0]), "r"(a[1]), "r"(a[2]), "r"(a[3]), "r"(b[0]), "r"(b[1]));
}

__global__ void __launch_bounds__(NTHREADS, 2)
poly_attn_mma(const float* __restrict__ q, const float* __restrict__ k,
              const float* __restrict__ v, float* __restrict__ out) {
    extern __shared__ uint32_t sm[];
    float* smf = (float*)sm;
    const int tid = threadIdx.x;
    const int wid = tid >> 5, lane = tid & 31;
    const int tq = lane >> 2, tc = lane & 3;
    const int bh = blockIdx.y, mt = blockIdx.x;
    const int m0 = wid * 32;                  // warp owns rows m0..m0+31

    // ---- Q tile [128][64] -> bf16 hi/lo pairs ----
    {
        const float4* qg = (const float4*)(q + ((size_t)bh * SLEN + (size_t)mt * BM) * DDIM);
#pragma unroll
        for (int r = 0; r < 16; r++) {
            int i4 = tid + r * NTHREADS;
            int row = i4 >> 4, pr = (i4 & 15) * 2;
            float4 x = qg[i4];
            float h0 = bfrt(x.x), h1 = bfrt(x.y), h2 = bfrt(x.z), h3 = bfrt(x.w);
            *(uint2*)(sm + OF_QH + row * LDQ2 + pr) =
                make_uint2(packbf(h1, h0), packbf(h3, h2));
            *(uint2*)(sm + OF_QL + row * LDQ2 + pr) =
                make_uint2(packbf(x.y - h1, x.x - h0), packbf(x.w - h3, x.z - h2));
        }
    }

    const float4* kg = (const float4*)(k + (size_t)bh * SLEN * DDIM);
    const float4* vg = (const float4*)(v + (size_t)bh * SLEN * DDIM);

    float4 kf[4], vf[4];
    auto store_tile = [&](int buf) {
        uint32_t* KH = sm + OF_KH + buf * BT * LDK2;
        uint32_t* KL = sm + OF_KL + buf * BT * LDK2;
        float* VB = smf + OF_V + buf * BT * LDV;
#pragma unroll
        for (int r = 0; r < 4; r++) {
            int i4 = tid + r * NTHREADS;
            int row = i4 >> 4, pr = (i4 & 15) * 2, c4 = (i4 & 15) * 4;
            float4 x = kf[r];
            float h0 = bfrt(x.x), h1 = bfrt(x.y), h2 = bfrt(x.z), h3 = bfrt(x.w);
            *(uint2*)(KH + row * LDK2 + pr) = make_uint2(packbf(h1, h0), packbf(h3, h2));
            *(uint2*)(KL + row * LDK2 + pr) =
                make_uint2(packbf(x.y - h1, x.x - h0), packbf(x.w - h3, x.z - h2));
            float4 y = vf[r];
            y.x = tf32_rna(y.x); y.y = tf32_rna(y.y);
            y.z = tf32_rna(y.z); y.w = tf32_rna(y.w);
            *(float4*)(VB + row * LDV + c4) = y;
        }
    };

    // prologue: tile0 -> buf0, prefetch tile1 (tile = BT*16 = 512 float4)
#pragma unroll
    for (int r = 0; r < 4; r++) { kf[r] = kg[tid + r * NTHREADS]; vf[r] = vg[tid + r * NTHREADS]; }
    store_tile(0);
#pragma unroll
    for (int r = 0; r < 4; r++) { kf[r] = kg[512 + tid + r * NTHREADS]; vf[r] = vg[512 + tid + r * NTHREADS]; }
    __syncthreads();

    float oacc[2][8][4];
    float dl[2] = {0.f, 0.f}, dh[2] = {0.f, 0.f};
#pragma unroll
    for (int t = 0; t < 2; t++)
#pragma unroll
        for (int ct = 0; ct < 8; ct++)
#pragma unroll
            for (int j = 0; j < 4; j++) oacc[t][ct][j] = 0.f;

    const int qoffh0 = OF_QH + (m0 + tq) * LDQ2 + tc;
    const int qoffl0 = OF_QL + (m0 + tq) * LDQ2 + tc;
    const int slo = 4 * tq + (tc >> 1);
    const int shi = slo + 2;
    const bool odd = (tc & 1);

    for (int nt = 0; nt < NITER; nt++) {
        const int buf = nt & 1;
        if (nt + 1 < NITER) store_tile(1 - buf);
        if (nt + 2 < NITER) {
#pragma unroll
            for (int r = 0; r < 4; r++) {
                kf[r] = kg[(nt + 2) * 512 + tid + r * NTHREADS];
                vf[r] = vg[(nt + 2) * 512 + tid + r * NTHREADS];
            }
        }

        const int KHo = OF_KH + buf * BT * LDK2;
        const int KLo = OF_KL + buf * BT * LDK2;
        const int Vo  = OF_V  + buf * BT * LDV;

        // ---- GEMM1: S[32x32] = (qh+ql)(kh+kl)^T (drop ql*kl); K frags shared ----
        float sacc[2][4][4];
#pragma unroll
        for (int t = 0; t < 2; t++)
#pragma unroll
            for (int ct = 0; ct < 4; ct++)
#pragma unroll
                for (int j = 0; j < 4; j++) sacc[t][ct][j] = 0.f;

#pragma unroll
        for (int ks = 0; ks < 4; ks++) {
            const int ko = ks * 8;
            uint32_t ah[2][4], al[2][4];
#pragma unroll
            for (int t = 0; t < 2; t++) {
                const int oh = qoffh0 + t * 16 * LDQ2 + ko;
                const int ol = qoffl0 + t * 16 * LDQ2 + ko;
                ah[t][0] = sm[oh];
                ah[t][1] = sm[oh + 8 * LDQ2];
                ah[t][2] = sm[oh + 4];
                ah[t][3] = sm[oh + 8 * LDQ2 + 4];
                al[t][0] = sm[ol];
                al[t][1] = sm[ol + 8 * LDQ2];
                al[t][2] = sm[ol + 4];
                al[t][3] = sm[ol + 8 * LDQ2 + 4];
            }
#pragma unroll
            for (int ct = 0; ct < 4; ct++) {
                const int o = (8 * ct + tq) * LDK2 + ko + tc;
                uint32_t bh2[2], bl2[2];
                bh2[0] = sm[KHo + o]; bh2[1] = sm[KHo + o + 4];
                bl2[0] = sm[KLo + o]; bl2[1] = sm[KLo + o + 4];
#pragma unroll
                for (int t = 0; t < 2; t++) {
                    mma16(sacc[t][ct], ah[t], bh2);
                    mma16(sacc[t][ct], ah[t], bl2);
                    mma16(sacc[t][ct], al[t], bh2);
                }
            }
        }

        // ---- epilogue: P = rna_tf32(S^2); denom partials ----
#pragma unroll
        for (int t = 0; t < 2; t++)
#pragma unroll
            for (int ct = 0; ct < 4; ct++) {
                sacc[t][ct][0] = tf32_rna(sacc[t][ct][0] * sacc[t][ct][0]);
                sacc[t][ct][1] = tf32_rna(sacc[t][ct][1] * sacc[t][ct][1]);
                sacc[t][ct][2] = tf32_rna(sacc[t][ct][2] * sacc[t][ct][2]);
                sacc[t][ct][3] = tf32_rna(sacc[t][ct][3] * sacc[t][ct][3]);
                dl[t] += sacc[t][ct][0] + sacc[t][ct][1];
                dh[t] += sacc[t][ct][2] + sacc[t][ct][3];
            }

        // ---- GEMM2 (tf32): O[32x64] += P[32x32] * V[32x64]; V frags shared ----
#pragma unroll
        for (int ks = 0; ks < 4; ks++) {
            uint32_t a[2][4];
#pragma unroll
            for (int t = 0; t < 2; t++) {
                float p0l = __shfl_sync(0xffffffffu, sacc[t][ks][0], slo);
                float p1l = __shfl_sync(0xffffffffu, sacc[t][ks][1], slo);
                float p2l = __shfl_sync(0xffffffffu, sacc[t][ks][2], slo);
                float p3l = __shfl_sync(0xffffffffu, sacc[t][ks][3], slo);
                float p0h = __shfl_sync(0xffffffffu, sacc[t][ks][0], shi);
                float p1h = __shfl_sync(0xffffffffu, sacc[t][ks][1], shi);
                float p2h = __shfl_sync(0xffffffffu, sacc[t][ks][2], shi);
                float p3h = __shfl_sync(0xffffffffu, sacc[t][ks][3], shi);
                a[t][0] = __float_as_uint(odd ? p1l : p0l);
                a[t][1] = __float_as_uint(odd ? p3l : p2l);
                a[t][2] = __float_as_uint(odd ? p1h : p0h);
                a[t][3] = __float_as_uint(odd ? p3h : p2h);
            }
            const int vk = Vo + (8 * ks + tc) * LDV + tq;
#pragma unroll
            for (int ct = 0; ct < 8; ct++) {
                uint32_t vb[2];
                vb[0] = sm[vk + 8 * ct];
                vb[1] = sm[vk + 4 * LDV + 8 * ct];
                mma8(oacc[0][ct], a[0], vb);
                mma8(oacc[1][ct], a[1], vb);
            }
        }
        __syncthreads();
    }

    // ---- denominator reduce over tc lanes; normalize and store ----
    float* og = out + ((size_t)bh * SLEN + (size_t)mt * BM + m0) * DDIM;
#pragma unroll
    for (int t = 0; t < 2; t++) {
        float l = dl[t], h = dh[t];
        l += __shfl_xor_sync(0xffffffffu, l, 1);
        l += __shfl_xor_sync(0xffffffffu, l, 2);
        h += __shfl_xor_sync(0xffffffffu, h, 1);
        h += __shfl_xor_sync(0xffffffffu, h, 2);
        const float il = 1.f / fmaxf(l, EPS_CLAMP);
        const float ih = 1.f / fmaxf(h, EPS_CLAMP);
#pragma unroll
        for (int ct = 0; ct < 8; ct++) {
            int dcol = 8 * ct + 2 * tc;
            *(float2*)(og + (size_t)(t * 16 + tq) * DDIM + dcol) =
                make_float2(oacc[t][ct][0] * il, oacc[t][ct][1] * il);
            *(float2*)(og + (size_t)(t * 16 + tq + 8) * DDIM + dcol) =
                make_float2(oacc[t][ct][2] * ih, oacc[t][ct][3] * ih);
        }
    }
}

extern "C" void kernel_launch(void* const* d_in, const int* in_sizes, int n_in,
                              void* d_out, int out_size) {
    (void)in_sizes; (void)n_in; (void)out_size;
    const float* q = (const float*)d_in[0];
    const float* k = (const float*)d_in[1];
    const float* v = (const float*)d_in[2];
    float* out = (float*)d_out;

    cudaFuncSetAttribute(poly_attn_mma,
                         cudaFuncAttributeMaxDynamicSharedMemorySize, SMEM_BYTES);
    poly_attn_mma<<<dim3(SLEN / BM, 32), NTHREADS, SMEM_BYTES>>>(q, k, v, out);
}

// round 9
// speedup vs baseline: 1.7254x; 1.7254x over previous
#include <cuda_runtime.h>
#include <cuda_bf16.h>
#include <cstdint>

// Polynomial attention deg-2, B=2 H=16 S=2048 D=64 fp32.
// GEMM1: bf16 2-term split, mma.m16n8k16. GEMM2: tf32 m16n8k8.
// BM=256 (warp owns 32 rows), BT=64, double-buffered.
// GEMM2 A-fragments come DIRECTLY from the GEMM1 accumulator via a key-axis
// permutation baked into the V smem layout (no shuffles).

#define SLEN 2048
#define DDIM 64
#define BM 256
#define BT 64
#define NITER (SLEN / BT)
#define EPS_CLAMP 1e-4f

#define LDQ2 36   // u32 ld: bank = 4*tq+tc, conflict-free
#define LDK2 36
#define LDV 72    // f32 ld: bank = 8*tc+tq, conflict-free

// smem offsets (4-byte units)
#define OF_QH 0
#define OF_QL (OF_QH + BM * LDQ2)
#define OF_KH (OF_QL + BM * LDQ2)          // [2][64][36]
#define OF_KL (OF_KH + 2 * BT * LDK2)
#define OF_V  (OF_KL + 2 * BT * LDK2)      // [2][64][72] f32 (rows permuted)
#define SMEM_U32 (OF_V + 2 * BT * LDV)
#define SMEM_BYTES (SMEM_U32 * 4)

__device__ __forceinline__ float tf32_rna(float x) {
    uint32_t u;
    asm("cvt.rna.tf32.f32 %0, %1;" : "=r"(u) : "f"(x));
    return __uint_as_float(u);
}
__device__ __forceinline__ uint32_t packbf(float hi, float lo) {
    uint32_t u;
    asm("cvt.rn.bf16x2.f32 %0, %1, %2;" : "=r"(u) : "f"(hi), "f"(lo));
    return u;
}
__device__ __forceinline__ float bfrt(float x) {
    return __bfloat162float(__float2bfloat16(x));
}
__device__ __forceinline__ void mma16(float* d, const uint32_t* a, const uint32_t* b) {
    asm("mma.sync.aligned.m16n8k16.row.col.f32.bf16.bf16.f32 "
        "{%0,%1,%2,%3}, {%4,%5,%6,%7}, {%8,%9}, {%0,%1,%2,%3};"
        : "+f"(d[0]), "+f"(d[1]), "+f"(d[2]), "+f"(d[3])
        : "r"(a[0]), "r"(a[1]), "r"(a[2]), "r"(a[3]), "r"(b[0]), "r"(b[1]));
}
__device__ __forceinline__ void mma8(float* d, const uint32_t* a, const uint32_t* b) {
    asm("mma.sync.aligned.m16n8k8.row.col.f32.tf32.tf32.f32 "
        "{%0,%1,%2,%3}, {%4,%5,%6,%7}, {%8,%9}, {%0,%1,%2,%3};"
        : "+f"(d[0]), "+f"(d[1]), "+f"(d[2]), "+f"(d[3])
        : "r"(a[0]), "r"(a[1]), "r"(a[2]), "r"(a[3]), "r"(b[0]), "r"(b[1]));
}

__global__ void __launch_bounds__(256, 1)
poly_attn_mma(const float* __restrict__ q, const float* __restrict__ k,
              const float* __restrict__ v, float* __restrict__ out) {
    extern __shared__ uint32_t sm[];
    float* smf = (float*)sm;
    const int tid = threadIdx.x;
    const int wid = tid >> 5, lane = tid & 31;
    const int tq = lane >> 2, tc = lane & 3;
    const int bh = blockIdx.y, mt = blockIdx.x;
    const int m0 = wid * 32;                  // warp owns rows m0..m0+31

    // ---- Q tile [256][64] -> bf16 hi/lo pairs ----
    {
        const float4* qg = (const float4*)(q + ((size_t)bh * SLEN + (size_t)mt * BM) * DDIM);
#pragma unroll
        for (int r = 0; r < 16; r++) {
            int i4 = tid + r * 256;
            int row = i4 >> 4, pr = (i4 & 15) * 2;
            float4 x = qg[i4];
            float h0 = bfrt(x.x), h1 = bfrt(x.y), h2 = bfrt(x.z), h3 = bfrt(x.w);
            *(uint2*)(sm + OF_QH + row * LDQ2 + pr) =
                make_uint2(packbf(h1, h0), packbf(h3, h2));
            *(uint2*)(sm + OF_QL + row * LDQ2 + pr) =
                make_uint2(packbf(x.y - h1, x.x - h0), packbf(x.w - h3, x.z - h2));
        }
    }

    const float4* kg = (const float4*)(k + (size_t)bh * SLEN * DDIM);
    const float4* vg = (const float4*)(v + (size_t)bh * SLEN * DDIM);

    float4 kf[4], vf[4];
    auto store_tile = [&](int buf) {
        uint32_t* KH = sm + OF_KH + buf * BT * LDK2;
        uint32_t* KL = sm + OF_KL + buf * BT * LDK2;
        float* VB = smf + OF_V + buf * BT * LDV;
#pragma unroll
        for (int r = 0; r < 4; r++) {
            int i4 = tid + r * 256;
            int row = i4 >> 4, pr = (i4 & 15) * 2, c4 = (i4 & 15) * 4;
            float4 x = kf[r];
            float h0 = bfrt(x.x), h1 = bfrt(x.y), h2 = bfrt(x.z), h3 = bfrt(x.w);
            *(uint2*)(KH + row * LDK2 + pr) = make_uint2(packbf(h1, h0), packbf(h3, h2));
            *(uint2*)(KL + row * LDK2 + pr) =
                make_uint2(packbf(x.y - h1, x.x - h0), packbf(x.w - h3, x.z - h2));
            // V row permuted within each 8-key group: slot j' for actual key j
            // j even -> j/2 ; j odd -> 4 + j/2   (inverse of pi(f)=2f / 2(f-4)+1)
            int j = row & 7;
            int vrow = (row & ~7) | ((j & 1) ? (4 + (j >> 1)) : (j >> 1));
            float4 y = vf[r];
            y.x = tf32_rna(y.x); y.y = tf32_rna(y.y);
            y.z = tf32_rna(y.z); y.w = tf32_rna(y.w);
            *(float4*)(VB + vrow * LDV + c4) = y;
        }
    };

#pragma unroll
    for (int r = 0; r < 4; r++) { kf[r] = kg[tid + r * 256]; vf[r] = vg[tid + r * 256]; }
    store_tile(0);
#pragma unroll
    for (int r = 0; r < 4; r++) { kf[r] = kg[1024 + tid + r * 256]; vf[r] = vg[1024 + tid + r * 256]; }
    __syncthreads();

    float oacc[2][8][4];
    float dl[2] = {0.f, 0.f}, dh[2] = {0.f, 0.f};
#pragma unroll
    for (int t = 0; t < 2; t++)
#pragma unroll
        for (int ct = 0; ct < 8; ct++)
#pragma unroll
            for (int j = 0; j < 4; j++) oacc[t][ct][j] = 0.f;

    const int qoffh0 = OF_QH + (m0 + tq) * LDQ2 + tc;
    const int qoffl0 = OF_QL + (m0 + tq) * LDQ2 + tc;

    for (int nt = 0; nt < NITER; nt++) {
        const int buf = nt & 1;
        if (nt + 1 < NITER) store_tile(1 - buf);
        if (nt + 2 < NITER) {
#pragma unroll
            for (int r = 0; r < 4; r++) {
                kf[r] = kg[(nt + 2) * 1024 + tid + r * 256];
                vf[r] = vg[(nt + 2) * 1024 + tid + r * 256];
            }
        }

        const int KHo = OF_KH + buf * BT * LDK2;
        const int KLo = OF_KL + buf * BT * LDK2;
        const int Vo  = OF_V  + buf * BT * LDV;

        // ---- GEMM1: S[32x64] = (qh+ql)(kh+kl)^T (drop ql*kl); K frags shared ----
        float sacc[2][8][4];
#pragma unroll
        for (int t = 0; t < 2; t++)
#pragma unroll
            for (int ct = 0; ct < 8; ct++)
#pragma unroll
                for (int j = 0; j < 4; j++) sacc[t][ct][j] = 0.f;

#pragma unroll
        for (int ks = 0; ks < 4; ks++) {
            const int ko = ks * 8;
            uint32_t ah[2][4], al[2][4];
#pragma unroll
            for (int t = 0; t < 2; t++) {
                const int oh = qoffh0 + t * 16 * LDQ2 + ko;
                const int ol = qoffl0 + t * 16 * LDQ2 + ko;
                ah[t][0] = sm[oh];
                ah[t][1] = sm[oh + 8 * LDQ2];
                ah[t][2] = sm[oh + 4];
                ah[t][3] = sm[oh + 8 * LDQ2 + 4];
                al[t][0] = sm[ol];
                al[t][1] = sm[ol + 8 * LDQ2];
                al[t][2] = sm[ol + 4];
                al[t][3] = sm[ol + 8 * LDQ2 + 4];
            }
#pragma unroll
            for (int ct = 0; ct < 8; ct++) {
                const int o = (8 * ct + tq) * LDK2 + ko + tc;
                uint32_t bh2[2], bl2[2];
                bh2[0] = sm[KHo + o]; bh2[1] = sm[KHo + o + 4];
                bl2[0] = sm[KLo + o]; bl2[1] = sm[KLo + o + 4];
#pragma unroll
                for (int t = 0; t < 2; t++) {
                    mma16(sacc[t][ct], ah[t], bh2);
                    mma16(sacc[t][ct], ah[t], bl2);
                    mma16(sacc[t][ct], al[t], bh2);
                }
            }
        }

        // ---- epilogue: P = rna_tf32(S^2); denom partials ----
#pragma unroll
        for (int t = 0; t < 2; t++)
#pragma unroll
            for (int ct = 0; ct < 8; ct++) {
                sacc[t][ct][0] = tf32_rna(sacc[t][ct][0] * sacc[t][ct][0]);
                sacc[t][ct][1] = tf32_rna(sacc[t][ct][1] * sacc[t][ct][1]);
                sacc[t][ct][2] = tf32_rna(sacc[t][ct][2] * sacc[t][ct][2]);
                sacc[t][ct][3] = tf32_rna(sacc[t][ct][3] * sacc[t][ct][3]);
                dl[t] += sacc[t][ct][0] + sacc[t][ct][1];
                dh[t] += sacc[t][ct][2] + sacc[t][ct][3];
            }

        // ---- GEMM2 (tf32): O[32x64] += P * V_perm; A = acc regs directly ----
        // A-frag for key-group g: {c0, c2, c1, c3} of sacc[t][g]
        // (acc cols 2tc,2tc+1 == permuted frag-k tc,tc+4; V rows stored permuted)
#pragma unroll
        for (int g = 0; g < 8; g++) {
            uint32_t a[2][4];
#pragma unroll
            for (int t = 0; t < 2; t++) {
                a[t][0] = __float_as_uint(sacc[t][g][0]);
                a[t][1] = __float_as_uint(sacc[t][g][2]);
                a[t][2] = __float_as_uint(sacc[t][g][1]);
                a[t][3] = __float_as_uint(sacc[t][g][3]);
            }
            const int vk = Vo + (8 * g + tc) * LDV + tq;
#pragma unroll
            for (int ct = 0; ct < 8; ct++) {
                uint32_t vb[2];
                vb[0] = sm[vk + 8 * ct];
                vb[1] = sm[vk + 4 * LDV + 8 * ct];
                mma8(oacc[0][ct], a[0], vb);
                mma8(oacc[1][ct], a[1], vb);
            }
        }
        __syncthreads();
    }

    // ---- denominator reduce over tc lanes; normalize and store ----
    float* og = out + ((size_t)bh * SLEN + (size_t)mt * BM + m0) * DDIM;
#pragma unroll
    for (int t = 0; t < 2; t++) {
        float l = dl[t], h = dh[t];
        l += __shfl_xor_sync(0xffffffffu, l, 1);
        l += __shfl_xor_sync(0xffffffffu, l, 2);
        h += __shfl_xor_sync(0xffffffffu, h, 1);
        h += __shfl_xor_sync(0xffffffffu, h, 2);
        const float il = 1.f / fmaxf(l, EPS_CLAMP);
        const float ih = 1.f / fmaxf(h, EPS_CLAMP);
#pragma unroll
        for (int ct = 0; ct < 8; ct++) {
            int dcol = 8 * ct + 2 * tc;
            *(float2*)(og + (size_t)(t * 16 + tq) * DDIM + dcol) =
                make_float2(oacc[t][ct][0] * il, oacc[t][ct][1] * il);
            *(float2*)(og + (size_t)(t * 16 + tq + 8) * DDIM + dcol) =
                make_float2(oacc[t][ct][2] * ih, oacc[t][ct][3] * ih);
        }
    }
}

extern "C" void kernel_launch(void* const* d_in, const int* in_sizes, int n_in,
                              void* d_out, int out_size) {
    (void)in_sizes; (void)n_in; (void)out_size;
    const float* q = (const float*)d_in[0];
    const float* k = (const float*)d_in[1];
    const float* v = (const float*)d_in[2];
    float* out = (float*)d_out;

    cudaFuncSetAttribute(poly_attn_mma,
                         cudaFuncAttributeMaxDynamicSharedMemorySize, SMEM_BYTES);
    poly_attn_mma<<<dim3(SLEN / BM, 32), 256, SMEM_BYTES>>>(q, k, v, out);
}

// round 10
// speedup vs baseline: 1.7261x; 1.0004x over previous
#include <cuda_runtime.h>
#include <cuda_bf16.h>
#include <cstdint>

// Polynomial attention deg-2, B=2 H=16 S=2048 D=64 fp32.
// GEMM1: bf16 2-term split, mma.m16n8k16. GEMM2: tf32 m16n8k8, A-frags direct
// from GEMM1 accumulator via key-permutation baked into V layout.
// K-split/V-round precomputed to global scratch; tiles staged via cp.async.

#define NBH 32
#define SLEN 2048
#define DDIM 64
#define BM 256
#define BT 64
#define NITER (SLEN / BT)
#define EPS_CLAMP 1e-4f

#define LDQ2 36
#define LDK2 36
#define LDV 72

// smem offsets (4-byte units)
#define OF_QH 0
#define OF_QL (OF_QH + BM * LDQ2)
#define OF_KH (OF_QL + BM * LDQ2)          // [2][64][36] u32 (bf16 pairs)
#define OF_KL (OF_KH + 2 * BT * LDK2)
#define OF_V  (OF_KL + 2 * BT * LDK2)      // [2][64][72] f32 (rows permuted)
#define SMEM_U32 (OF_V + 2 * BT * LDV)
#define SMEM_BYTES (SMEM_U32 * 4)

// global scratch: packed bf16-pair splits of K, rna-rounded V
__device__ uint32_t g_KH[(size_t)NBH * SLEN * 32];
__device__ uint32_t g_KL[(size_t)NBH * SLEN * 32];
__device__ float    g_Vr[(size_t)NBH * SLEN * DDIM];

__device__ __forceinline__ float tf32_rna(float x) {
    uint32_t u;
    asm("cvt.rna.tf32.f32 %0, %1;" : "=r"(u) : "f"(x));
    return __uint_as_float(u);
}
__device__ __forceinline__ uint32_t packbf(float hi, float lo) {
    uint32_t u;
    asm("cvt.rn.bf16x2.f32 %0, %1, %2;" : "=r"(u) : "f"(hi), "f"(lo));
    return u;
}
__device__ __forceinline__ float bfrt(float x) {
    return __bfloat162float(__float2bfloat16(x));
}
__device__ __forceinline__ uint32_t smem_u32addr(const void* p) {
    uint32_t a;
    asm("{ .reg .u64 t; cvta.to.shared.u64 t, %1; cvt.u32.u64 %0, t; }"
        : "=r"(a) : "l"(p));
    return a;
}
__device__ __forceinline__ void cp16(uint32_t dst, const void* src) {
    asm volatile("cp.async.cg.shared.global [%0], [%1], 16;"
                 :: "r"(dst), "l"(src));
}
__device__ __forceinline__ void mma16(float* d, const uint32_t* a, const uint32_t* b) {
    asm("mma.sync.aligned.m16n8k16.row.col.f32.bf16.bf16.f32 "
        "{%0,%1,%2,%3}, {%4,%5,%6,%7}, {%8,%9}, {%0,%1,%2,%3};"
        : "+f"(d[0]), "+f"(d[1]), "+f"(d[2]), "+f"(d[3])
        : "r"(a[0]), "r"(a[1]), "r"(a[2]), "r"(a[3]), "r"(b[0]), "r"(b[1]));
}
__device__ __forceinline__ void mma8(float* d, const uint32_t* a, const uint32_t* b) {
    asm("mma.sync.aligned.m16n8k8.row.col.f32.tf32.tf32.f32 "
        "{%0,%1,%2,%3}, {%4,%5,%6,%7}, {%8,%9}, {%0,%1,%2,%3};"
        : "+f"(d[0]), "+f"(d[1]), "+f"(d[2]), "+f"(d[3])
        : "r"(a[0]), "r"(a[1]), "r"(a[2]), "r"(a[3]), "r"(b[0]), "r"(b[1]));
}

// ---- precompute: K -> (KH,KL) packed bf16 pairs, V -> rna-rounded f32 ----
// one thread per 16 consecutive elements
__global__ void precompute_kv(const float* __restrict__ k,
                              const float* __restrict__ v) {
    size_t i = (size_t)blockIdx.x * blockDim.x + threadIdx.x;
    const float4* k4 = (const float4*)k;
    const float4* v4 = (const float4*)v;
    uint4 H[2], L[2];
    uint32_t* hp = (uint32_t*)H;
    uint32_t* lp = (uint32_t*)L;
#pragma unroll
    for (int r = 0; r < 4; r++) {
        float4 x = k4[i * 4 + r];
        float h0 = bfrt(x.x), h1 = bfrt(x.y), h2 = bfrt(x.z), h3 = bfrt(x.w);
        hp[r * 2 + 0] = packbf(h1, h0);
        hp[r * 2 + 1] = packbf(h3, h2);
        lp[r * 2 + 0] = packbf(x.y - h1, x.x - h0);
        lp[r * 2 + 1] = packbf(x.w - h3, x.z - h2);
    }
    ((uint4*)g_KH)[i * 2 + 0] = H[0];
    ((uint4*)g_KH)[i * 2 + 1] = H[1];
    ((uint4*)g_KL)[i * 2 + 0] = L[0];
    ((uint4*)g_KL)[i * 2 + 1] = L[1];
#pragma unroll
    for (int r = 0; r < 4; r++) {
        float4 y = v4[i * 4 + r];
        y.x = tf32_rna(y.x); y.y = tf32_rna(y.y);
        y.z = tf32_rna(y.z); y.w = tf32_rna(y.w);
        ((float4*)g_Vr)[i * 4 + r] = y;
    }
}

__global__ void __launch_bounds__(256, 1)
poly_attn_mma(const float* __restrict__ q, float* __restrict__ out) {
    extern __shared__ uint32_t sm[];
    const uint32_t sb = smem_u32addr(sm);
    const int tid = threadIdx.x;
    const int wid = tid >> 5, lane = tid & 31;
    const int tq = lane >> 2, tc = lane & 3;
    const int bh = blockIdx.y, mt = blockIdx.x;
    const int m0 = wid * 32;

    // ---- Q tile [256][64] -> bf16 hi/lo pairs (once) ----
    {
        const float4* qg = (const float4*)(q + ((size_t)bh * SLEN + (size_t)mt * BM) * DDIM);
#pragma unroll
        for (int r = 0; r < 16; r++) {
            int i4 = tid + r * 256;
            int row = i4 >> 4, pr = (i4 & 15) * 2;
            float4 x = qg[i4];
            float h0 = bfrt(x.x), h1 = bfrt(x.y), h2 = bfrt(x.z), h3 = bfrt(x.w);
            *(uint2*)(sm + OF_QH + row * LDQ2 + pr) =
                make_uint2(packbf(h1, h0), packbf(h3, h2));
            *(uint2*)(sm + OF_QL + row * LDQ2 + pr) =
                make_uint2(packbf(x.y - h1, x.x - h0), packbf(x.w - h3, x.z - h2));
        }
    }

    // ---- async tile stage: 8x16B per thread, zero registers ----
    auto issue_tile = [&](int nt, int buf) {
        const uint32_t* gKH = g_KH + ((size_t)bh * SLEN + nt * BT) * 32;
        const uint32_t* gKL = g_KL + ((size_t)bh * SLEN + nt * BT) * 32;
        const float* gV = g_Vr + ((size_t)bh * SLEN + nt * BT) * DDIM;
#pragma unroll
        for (int j = 0; j < 2; j++) {
            int cc = tid + j * 256;
            int row = cc >> 3, o4 = (cc & 7) * 4;
            cp16(sb + (uint32_t)(OF_KH + buf * BT * LDK2 + row * LDK2 + o4) * 4,
                 gKH + row * 32 + o4);
            cp16(sb + (uint32_t)(OF_KL + buf * BT * LDK2 + row * LDK2 + o4) * 4,
                 gKL + row * 32 + o4);
        }
#pragma unroll
        for (int j = 0; j < 4; j++) {
            int cc = tid + j * 256;
            int row = cc >> 4, o4 = (cc & 15) * 4;
            int jj = row & 7;   // V row permutation (matches GEMM2 A-frag layout)
            int vrow = (row & ~7) | ((jj & 1) ? (4 + (jj >> 1)) : (jj >> 1));
            cp16(sb + (uint32_t)(OF_V + buf * BT * LDV + vrow * LDV + o4) * 4,
                 gV + row * DDIM + o4);
        }
        asm volatile("cp.async.commit_group;" ::: "memory");
    };

    issue_tile(0, 0);
    issue_tile(1, 1);
    asm volatile("cp.async.wait_group 1;" ::: "memory");   // tile 0 landed
    __syncthreads();

    float oacc[2][8][4];
    float dl[2] = {0.f, 0.f}, dh[2] = {0.f, 0.f};
#pragma unroll
    for (int t = 0; t < 2; t++)
#pragma unroll
        for (int ct = 0; ct < 8; ct++)
#pragma unroll
            for (int j = 0; j < 4; j++) oacc[t][ct][j] = 0.f;

    const int qoffh0 = OF_QH + (m0 + tq) * LDQ2 + tc;
    const int qoffl0 = OF_QL + (m0 + tq) * LDQ2 + tc;

    for (int nt = 0; nt < NITER; nt++) {
        const int buf = nt & 1;
        const int KHo = OF_KH + buf * BT * LDK2;
        const int KLo = OF_KL + buf * BT * LDK2;
        const int Vo  = OF_V  + buf * BT * LDV;

        // ---- GEMM1: S[32x64] = (qh+ql)(kh+kl)^T (drop ql*kl) ----
        float sacc[2][8][4];
#pragma unroll
        for (int t = 0; t < 2; t++)
#pragma unroll
            for (int ct = 0; ct < 8; ct++)
#pragma unroll
                for (int j = 0; j < 4; j++) sacc[t][ct][j] = 0.f;

#pragma unroll
        for (int ks = 0; ks < 4; ks++) {
            const int ko = ks * 8;
            uint32_t ah[2][4], al[2][4];
#pragma unroll
            for (int t = 0; t < 2; t++) {
                const int oh = qoffh0 + t * 16 * LDQ2 + ko;
                const int ol = qoffl0 + t * 16 * LDQ2 + ko;
                ah[t][0] = sm[oh];
                ah[t][1] = sm[oh + 8 * LDQ2];
                ah[t][2] = sm[oh + 4];
                ah[t][3] = sm[oh + 8 * LDQ2 + 4];
                al[t][0] = sm[ol];
                al[t][1] = sm[ol + 8 * LDQ2];
                al[t][2] = sm[ol + 4];
                al[t][3] = sm[ol + 8 * LDQ2 + 4];
            }
#pragma unroll
            for (int ct = 0; ct < 8; ct++) {
                const int o = (8 * ct + tq) * LDK2 + ko + tc;
                uint32_t bh2[2], bl2[2];
                bh2[0] = sm[KHo + o]; bh2[1] = sm[KHo + o + 4];
                bl2[0] = sm[KLo + o]; bl2[1] = sm[KLo + o + 4];
#pragma unroll
                for (int t = 0; t < 2; t++) {
                    mma16(sacc[t][ct], ah[t], bh2);
                    mma16(sacc[t][ct], ah[t], bl2);
                    mma16(sacc[t][ct], al[t], bh2);
                }
            }
        }

        // ---- epilogue: P = rna_tf32(S^2); denom partials ----
#pragma unroll
        for (int t = 0; t < 2; t++)
#pragma unroll
            for (int ct = 0; ct < 8; ct++) {
                sacc[t][ct][0] = tf32_rna(sacc[t][ct][0] * sacc[t][ct][0]);
                sacc[t][ct][1] = tf32_rna(sacc[t][ct][1] * sacc[t][ct][1]);
                sacc[t][ct][2] = tf32_rna(sacc[t][ct][2] * sacc[t][ct][2]);
                sacc[t][ct][3] = tf32_rna(sacc[t][ct][3] * sacc[t][ct][3]);
                dl[t] += sacc[t][ct][0] + sacc[t][ct][1];
                dh[t] += sacc[t][ct][2] + sacc[t][ct][3];
            }

        // ---- GEMM2 (tf32): O += P * V_perm; A-frag = acc regs {0,2,1,3} ----
#pragma unroll
        for (int g = 0; g < 8; g++) {
            uint32_t a[2][4];
#pragma unroll
            for (int t = 0; t < 2; t++) {
                a[t][0] = __float_as_uint(sacc[t][g][0]);
                a[t][1] = __float_as_uint(sacc[t][g][2]);
                a[t][2] = __float_as_uint(sacc[t][g][1]);
                a[t][3] = __float_as_uint(sacc[t][g][3]);
            }
            const int vk = Vo + (8 * g + tc) * LDV + tq;
#pragma unroll
            for (int ct = 0; ct < 8; ct++) {
                uint32_t vb[2];
                vb[0] = sm[vk + 8 * ct];
                vb[1] = sm[vk + 4 * LDV + 8 * ct];
                mma8(oacc[0][ct], a[0], vb);
                mma8(oacc[1][ct], a[1], vb);
            }
        }

        if (nt + 1 < NITER)
            asm volatile("cp.async.wait_group 0;" ::: "memory");  // tile nt+1 landed
        __syncthreads();    // all warps done with tile nt; tile nt+1 visible
        if (nt + 2 < NITER) issue_tile(nt + 2, buf);
    }

    // ---- denominator reduce over tc lanes; normalize and store ----
    float* og = out + ((size_t)bh * SLEN + (size_t)mt * BM + m0) * DDIM;
#pragma unroll
    for (int t = 0; t < 2; t++) {
        float l = dl[t], h = dh[t];
        l += __shfl_xor_sync(0xffffffffu, l, 1);
        l += __shfl_xor_sync(0xffffffffu, l, 2);
        h += __shfl_xor_sync(0xffffffffu, h, 1);
        h += __shfl_xor_sync(0xffffffffu, h, 2);
        const float il = 1.f / fmaxf(l, EPS_CLAMP);
        const float ih = 1.f / fmaxf(h, EPS_CLAMP);
#pragma unroll
        for (int ct = 0; ct < 8; ct++) {
            int dcol = 8 * ct + 2 * tc;
            *(float2*)(og + (size_t)(t * 16 + tq) * DDIM + dcol) =
                make_float2(oacc[t][ct][0] * il, oacc[t][ct][1] * il);
            *(float2*)(og + (size_t)(t * 16 + tq + 8) * DDIM + dcol) =
                make_float2(oacc[t][ct][2] * ih, oacc[t][ct][3] * ih);
        }
    }
}

extern "C" void kernel_launch(void* const* d_in, const int* in_sizes, int n_in,
                              void* d_out, int out_size) {
    (void)in_sizes; (void)n_in; (void)out_size;
    const float* q = (const float*)d_in[0];
    const float* k = (const float*)d_in[1];
    const float* v = (const float*)d_in[2];
    float* out = (float*)d_out;

    // total elements = 32*2048*64 = 4,194,304; one thread per 16 -> 262,144
    precompute_kv<<<1024, 256>>>(k, v);

    cudaFuncSetAttribute(poly_attn_mma,
                         cudaFuncAttributeMaxDynamicSharedMemorySize, SMEM_BYTES);
    poly_attn_mma<<<dim3(SLEN / BM, NBH), 256, SMEM_BYTES>>>(q, out);
}